// round 5
// baseline (speedup 1.0000x reference)
#include <cuda_runtime.h>

// ---------------------------------------------------------------------------
// PhotonicLayer: out[b,n] = Re[ (sum_m x[b,m] * U[n,m]) * exp(i*KERR*|.|^2) ]
// Output dtype is float32 (real part) — established by R4 diagnostics.
// Kernel 1: build U (one block, 64 threads, register-carry scan per column).
// Kernel 2: complex GEMM [B,64]x[64,64]^T + Kerr phase, fp32 SIMT, real store.
// ---------------------------------------------------------------------------

#define SIZE 64
#define NPH 2016
#define LOSS_AMP 0.9942600740f      // 10^(-0.05/20)
#define KERR 2.6e-17f               // NONLINEAR_COEFF * 1000
#define BB 128
#define XPITCH 129                  // mod 32 == 1 -> conflict-free transpose
#define OPITCH 65

__device__ float2 g_W[SIZE * SIZE]; // W[n*64+m] = U[n][m]

// ---------------------------- build kernel --------------------------------
__global__ void build_u_kernel(const float* __restrict__ phases, int nph) {
    __shared__ float2 S[SIZE][SIZE];    // 32 KB
    __shared__ float cs[NPH];
    __shared__ float sn[NPH];

    const int t = threadIdx.x;          // column 0..63
    const int pmax = (nph > 0) ? (nph - 1) : 0;

    for (int k = t; k < NPH; k += SIZE) {
        const int kk = (k < pmax) ? k : pmax;
        float sv, cv;
        sincosf(phases[kk], &sv, &cv);
        cs[k] = LOSS_AMP * cv;
        sn[k] = LOSS_AMP * sv;
    }
    for (int r = 0; r < SIZE; ++r)
        S[r][t] = make_float2(r == t ? 1.0f : 0.0f, 0.0f);
    __syncthreads();

    // each thread owns its column; register carry down each layer
    int k = 0;
    for (int i = 1; i < SIZE; ++i) {
        float ar = S[0][t].x, ai = S[0][t].y;
        for (int j = 0; j < i; ++j, ++k) {
            const float cc = cs[k], ss = sn[k];
            const float2 b = S[j + 1][t];
            const float nar = fmaf(cc, ar, -ss * b.y);
            const float nai = fmaf(cc, ai,  ss * b.x);
            const float nbr = fmaf(cc, b.x, -ss * ai);
            const float nbi = fmaf(cc, b.y,  ss * ar);
            S[j][t] = make_float2(nar, nai);
            ar = nbr; ai = nbi;
        }
        S[i][t] = make_float2(ar, ai);
    }
    __syncthreads();

    for (int n = 0; n < SIZE; ++n)
        g_W[n * SIZE + t] = S[n][t];
}

// ----------------------------- GEMM kernel --------------------------------
// 256 threads; tile 128 batches x 64 outputs; K=64 resident in shared.
__global__ __launch_bounds__(256, 2)
void photonic_gemm_kernel(const float* __restrict__ xr_g,
                          const float* __restrict__ xi_g,
                          float* __restrict__ out,
                          long long xsz,            // x element count (floats)
                          long long out_elems,      // out_size (float elements)
                          int B) {
    extern __shared__ char smem[];
    float2* su   = (float2*)smem;                     // [0, 32768)
    float*  sxr  = (float*)(smem + 32768);            // [32768, 65792)
    float*  sxi  = (float*)(smem + 32768 + 33024);    // [65792, 98816)
    float*  sout = (float*)(smem + 32768);            // reuse: 128*65*4 B

    const int tid  = threadIdx.x;
    const int lane = tid & 31;
    const int warp = tid >> 5;

    const long long b0 = (long long)blockIdx.x * BB;
    if (b0 >= B) return;

    // stage U (coalesced 64-bit loads)
    for (int p = tid; p < SIZE * SIZE; p += 256)
        su[p] = g_W[p];

    // stage x transposed: sx[m][b]
    const long long base = b0 * SIZE;
    const long long xmax = xsz - 1;
    for (int p = tid; p < BB * SIZE; p += 256) {
        const int b = p >> 6;
        const int m = p & 63;
        long long gi = base + p;
        if (gi > xmax) gi = xmax;
        sxr[m * XPITCH + b] = xr_g[gi];
        sxi[m * XPITCH + b] = xi_g[gi];
    }
    __syncthreads();

    // acc[n=8][b=4] complex
    float accr[8][4], acci[8][4];
    #pragma unroll
    for (int i = 0; i < 8; ++i)
        #pragma unroll
        for (int j = 0; j < 4; ++j) { accr[i][j] = 0.0f; acci[i][j] = 0.0f; }

    const int nbase = warp * 8;
    #pragma unroll 2
    for (int m = 0; m < SIZE; ++m) {
        float2 u[8];
        #pragma unroll
        for (int i = 0; i < 8; ++i) u[i] = su[(nbase + i) * SIZE + m]; // bcast
        float xr[4], xi[4];
        #pragma unroll
        for (int j = 0; j < 4; ++j) {
            xr[j] = sxr[m * XPITCH + lane + 32 * j];
            xi[j] = sxi[m * XPITCH + lane + 32 * j];
        }
        #pragma unroll
        for (int i = 0; i < 8; ++i)
            #pragma unroll
            for (int j = 0; j < 4; ++j) {
                accr[i][j] = fmaf( xr[j], u[i].x, accr[i][j]);
                accr[i][j] = fmaf(-xi[j], u[i].y, accr[i][j]);
                acci[i][j] = fmaf( xr[j], u[i].y, acci[i][j]);
                acci[i][j] = fmaf( xi[j], u[i].x, acci[i][j]);
            }
    }
    __syncthreads();   // x consumed; reuse shared for output staging

    // Kerr phase; keep only REAL part (output dtype is float32)
    #pragma unroll
    for (int i = 0; i < 8; ++i) {
        const int n = nbase + i;
        #pragma unroll
        for (int j = 0; j < 4; ++j) {
            const int b = lane + 32 * j;
            const float re = accr[i][j], im = acci[i][j];
            const float ph = KERR * (re * re + im * im);
            float s, c;
            __sincosf(ph, &s, &c);
            sout[b * OPITCH + n] = fmaf(re, c, -im * s);
        }
    }
    __syncthreads();

    // coalesced float store, guarded by out element count
    float* op = out + base;
    for (int q = tid; q < BB * SIZE; q += 256) {
        if (base + q < out_elems)
            op[q] = sout[(q >> 6) * OPITCH + (q & 63)];
    }
}

// ------------------------------- launch ------------------------------------
extern "C" void kernel_launch(void* const* d_in, const int* in_sizes, int n_in,
                              void* d_out, int out_size) {
    if (n_in < 3) return;

    // phases = the input with the smallest element count (2016 vs B*64)
    int ph_idx = 0;
    for (int i = 1; i < 3; ++i)
        if (in_sizes[i] < in_sizes[ph_idx]) ph_idx = i;

    const float* xr = nullptr;
    const float* xi = nullptr;
    long long xsz = 0;
    for (int i = 0; i < 3; ++i) {
        if (i == ph_idx) continue;
        if (!xr) { xr = (const float*)d_in[i]; xsz = in_sizes[i]; }
        else     { xi = (const float*)d_in[i]; }
    }
    const float* phases = (const float*)d_in[ph_idx];
    const int nph = in_sizes[ph_idx];

    const int B = (int)(xsz / SIZE);
    const int nblocks = (B + BB - 1) / BB;

    const int smem_bytes = 32768 + 2 * SIZE * XPITCH * 4;  // 98,816 B
    cudaFuncSetAttribute(photonic_gemm_kernel,
                         cudaFuncAttributeMaxDynamicSharedMemorySize,
                         smem_bytes);

    build_u_kernel<<<1, SIZE>>>(phases, nph);
    photonic_gemm_kernel<<<nblocks, 256, smem_bytes>>>(
        xr, xi, (float*)d_out, xsz, (long long)out_size, B);
}

// round 6
// speedup vs baseline: 1.0699x; 1.0699x over previous
#include <cuda_runtime.h>

// ---------------------------------------------------------------------------
// PhotonicLayer: out[b,n] = Re[(x @ U^T)[b,n] * exp(i*KERR*|.|^2)]  (float32)
// K1: build U — register-carry scan with depth-3 prefetch ring (no LDS stall).
// K2: complex GEMM via packed fma.rn.f32x2 (2x FFMA throughput on sm_103a).
// ---------------------------------------------------------------------------

#define SIZE 64
#define NPH 2016
#define LOSS_AMP 0.9942600740f      // 10^(-0.05/20)
#define KERR 2.6e-17f               // NONLINEAR_COEFF * 1000
#define BB 128
#define XPITCH 129                  // scalar x loads: conflict-free
#define UPITCH 66                   // even (LDS.64 aligned), 2-way only on stage
#define OPITCH 65

typedef unsigned long long u64t;

#define FFMA2(acc, a, b) \
    asm("fma.rn.f32x2 %0, %1, %2, %0;" : "+l"(acc) : "l"(a), "l"(b))
#define PACK2(d, lo, hi) \
    asm("mov.b64 %0, {%1, %2};" : "=l"(d) : "f"(lo), "f"(hi))
#define UNPACK2(lo, hi, v) \
    asm("mov.b64 {%0, %1}, %2;" : "=f"(lo), "=f"(hi) : "l"(v))

__device__ float2 g_W[SIZE * SIZE]; // W[n*64+m] = U[n][m]

// ---------------------------- build kernel --------------------------------
__global__ void build_u_kernel(const float* __restrict__ phases, int nph) {
    __shared__ float2 S[SIZE][SIZE];    // [row][col] 32 KB
    __shared__ float cs[NPH];
    __shared__ float sn[NPH];

    const int t = threadIdx.x;          // column 0..63
    const int pmax = (nph > 0) ? (nph - 1) : 0;

    for (int k = t; k < NPH; k += SIZE) {
        const int kk = (k < pmax) ? k : pmax;
        float sv, cv;
        sincosf(phases[kk], &sv, &cv);
        cs[k] = LOSS_AMP * cv;
        sn[k] = LOSS_AMP * sv;
    }
    for (int r = 0; r < SIZE; ++r)
        S[r][t] = make_float2(r == t ? 1.0f : 0.0f, 0.0f);
    __syncthreads();

    // serial scan; depth-3 prefetch ring hides LDS latency behind FFMA chain
    int k = 0;
    for (int i = 1; i < SIZE; ++i) {
        float ar = S[0][t].x, ai = S[0][t].y;
        float2 b0 = S[1][t];
        float2 b1 = S[2][t];
        float2 b2 = S[3][t];
        #pragma unroll 2
        for (int j = 0; j < i; ++j, ++k) {
            int pj = j + 4; pj = (pj > 63) ? 63 : pj;
            const float2 bn = S[pj][t];          // prefetch (indep of carry)
            const float cc = cs[k], ss = sn[k];
            const float nar = fmaf(cc, ar,   -(ss * b0.y));
            const float nai = fmaf(cc, ai,     ss * b0.x);
            const float nbr = fmaf(cc, b0.x, -(ss * ai));
            const float nbi = fmaf(cc, b0.y,   ss * ar);
            S[j][t] = make_float2(nar, nai);
            ar = nbr; ai = nbi;
            b0 = b1; b1 = b2; b2 = bn;
        }
        S[i][t] = make_float2(ar, ai);
    }
    __syncthreads();

    for (int n = 0; n < SIZE; ++n)
        g_W[n * SIZE + t] = S[n][t];
}

// ----------------------------- GEMM kernel --------------------------------
// 256 threads; tile 128 batches x 64 outputs; packed f32x2 over (n, n+1).
__global__ __launch_bounds__(256, 2)
void photonic_gemm_kernel(const float* __restrict__ xr_g,
                          const float* __restrict__ xi_g,
                          float* __restrict__ out,
                          long long xsz, long long out_elems, int B) {
    extern __shared__ char smem[];
    float* sur = (float*)smem;                         // 64*66*4 = 16896 B
    float* sui = (float*)(smem + 16896);               // 16896 B
    float* sxr = (float*)(smem + 33792);               // 64*129*4 = 33024 B
    float* sxi = (float*)(smem + 33792 + 33024);       // 33024 B
    float* sout = (float*)(smem + 33792);              // reuse: 128*65*4 B

    const int tid  = threadIdx.x;
    const int lane = tid & 31;
    const int warp = tid >> 5;

    const long long b0 = (long long)blockIdx.x * BB;
    if (b0 >= B) return;

    // stage U into re/im planes, transposed to [m][n] with pitch 66
    for (int p = tid; p < SIZE * SIZE; p += 256) {
        const int n = p >> 6, m = p & 63;
        const float2 w = g_W[p];
        sur[m * UPITCH + n] = w.x;
        sui[m * UPITCH + n] = w.y;
    }

    // stage x transposed: sx[m][b]
    const long long base = b0 * SIZE;
    const long long xmax = xsz - 1;
    for (int p = tid; p < BB * SIZE; p += 256) {
        const int bb = p >> 6, m = p & 63;
        long long gi = base + p;
        if (gi > xmax) gi = xmax;
        sxr[m * XPITCH + bb] = xr_g[gi];
        sxi[m * XPITCH + bb] = xi_g[gi];
    }
    __syncthreads();

    // packed accumulators: [n-pair k=0..3][batch j=0..3], lanes = (n, n+1)
    u64t accr[4][4], acci[4][4];
    #pragma unroll
    for (int kk = 0; kk < 4; ++kk)
        #pragma unroll
        for (int j = 0; j < 4; ++j) { accr[kk][j] = 0ull; acci[kk][j] = 0ull; }

    const int nbase = warp * 8;

    #pragma unroll 2
    for (int m = 0; m < SIZE; ++m) {
        // u pairs (broadcast, aligned LDS.64)
        u64t uxp[4], uyp[4];
        #pragma unroll
        for (int kk = 0; kk < 4; ++kk) {
            uxp[kk] = *(const u64t*)&sur[m * UPITCH + nbase + 2 * kk];
            uyp[kk] = *(const u64t*)&sui[m * UPITCH + nbase + 2 * kk];
        }
        // x scalars -> dup packs
        u64t xrd[4], xid[4], nxid[4];
        #pragma unroll
        for (int j = 0; j < 4; ++j) {
            const float xr = sxr[m * XPITCH + lane + 32 * j];
            const float xi = sxi[m * XPITCH + lane + 32 * j];
            const float nxi = -xi;
            PACK2(xrd[j], xr, xr);
            PACK2(xid[j], xi, xi);
            PACK2(nxid[j], nxi, nxi);
        }
        #pragma unroll
        for (int kk = 0; kk < 4; ++kk)
            #pragma unroll
            for (int j = 0; j < 4; ++j) {
                FFMA2(accr[kk][j], xrd[j],  uxp[kk]);
                FFMA2(accr[kk][j], nxid[j], uyp[kk]);
                FFMA2(acci[kk][j], xrd[j],  uyp[kk]);
                FFMA2(acci[kk][j], xid[j],  uxp[kk]);
            }
    }
    __syncthreads();   // x consumed; reuse shared for output staging

    // Kerr phase (ph ~ 1e-16): cos=1, sin=ph exactly in fp32 -> re - im*ph
    #pragma unroll
    for (int kk = 0; kk < 4; ++kk) {
        const int n = nbase + 2 * kk;
        #pragma unroll
        for (int j = 0; j < 4; ++j) {
            const int bidx = lane + 32 * j;
            float r0, r1, i0, i1;
            UNPACK2(r0, r1, accr[kk][j]);
            UNPACK2(i0, i1, acci[kk][j]);
            const float ph0 = KERR * fmaf(r0, r0, i0 * i0);
            const float ph1 = KERR * fmaf(r1, r1, i1 * i1);
            sout[bidx * OPITCH + n]     = fmaf(-i0, ph0, r0);
            sout[bidx * OPITCH + n + 1] = fmaf(-i1, ph1, r1);
        }
    }
    __syncthreads();

    // coalesced float store, guarded by out element count
    float* op = out + base;
    for (int q = tid; q < BB * SIZE; q += 256) {
        if (base + q < out_elems)
            op[q] = sout[(q >> 6) * OPITCH + (q & 63)];
    }
}

// ------------------------------- launch ------------------------------------
extern "C" void kernel_launch(void* const* d_in, const int* in_sizes, int n_in,
                              void* d_out, int out_size) {
    if (n_in < 3) return;

    // phases = the input with the smallest element count (2016 vs B*64)
    int ph_idx = 0;
    for (int i = 1; i < 3; ++i)
        if (in_sizes[i] < in_sizes[ph_idx]) ph_idx = i;

    const float* xr = nullptr;
    const float* xi = nullptr;
    long long xsz = 0;
    for (int i = 0; i < 3; ++i) {
        if (i == ph_idx) continue;
        if (!xr) { xr = (const float*)d_in[i]; xsz = in_sizes[i]; }
        else     { xi = (const float*)d_in[i]; }
    }
    const float* phases = (const float*)d_in[ph_idx];
    const int nph = in_sizes[ph_idx];

    const int B = (int)(xsz / SIZE);
    const int nblocks = (B + BB - 1) / BB;

    const int smem_bytes = 33792 + 2 * SIZE * XPITCH * 4;  // 99,840 B
    cudaFuncSetAttribute(photonic_gemm_kernel,
                         cudaFuncAttributeMaxDynamicSharedMemorySize,
                         smem_bytes);

    build_u_kernel<<<1, SIZE>>>(phases, nph);
    photonic_gemm_kernel<<<nblocks, 256, smem_bytes>>>(
        xr, xi, (float*)d_out, xsz, (long long)out_size, B);
}